// round 3
// baseline (speedup 1.0000x reference)
#include <cuda_runtime.h>

// LIF neuron, T=4 unrolled, 2 neurons per thread using Blackwell 256-bit
// vector loads (ld.global.v8.f32 -> LDG.E.256). Layout [B, N, T], T innermost:
// one float4 per neuron, one v8 per thread per input array.
// Stores via 128-bit streaming (__stcs). Exact-division fast path (no
// predicates); float4 fallback kernel for general sizes.

#define TAU 0.25f

__device__ __forceinline__ float4 lif4(float4 xv, float4 lv, float thre)
{
    float4 ov;
    float u = xv.x + lv.x;                 // t=0: u0=0 -> no decay term
    float o = (u > thre) ? u : 0.0f;
    ov.x = o;
    float reset = (o > thre) ? 0.0f : 1.0f;
    u = TAU * u * reset + xv.y + lv.y;     // t=1
    o = (u > thre) ? u : 0.0f;
    ov.y = o;
    reset = (o > thre) ? 0.0f : 1.0f;
    u = TAU * u * reset + xv.z + lv.z;     // t=2
    o = (u > thre) ? u : 0.0f;
    ov.z = o;
    reset = (o > thre) ? 0.0f : 1.0f;
    u = TAU * u * reset + xv.w + lv.w;     // t=3
    o = (u > thre) ? u : 0.0f;
    ov.w = o;
    return ov;
}

__device__ __forceinline__ void ldg256(const float* p,
                                       float4& a, float4& b)
{
    asm volatile(
        "ld.global.v8.f32 {%0,%1,%2,%3,%4,%5,%6,%7}, [%8];"
        : "=f"(a.x), "=f"(a.y), "=f"(a.z), "=f"(a.w),
          "=f"(b.x), "=f"(b.y), "=f"(b.z), "=f"(b.w)
        : "l"(p));
}

// Fast path: n_neurons divisible by 2*blockDim*grid covered exactly.
__global__ __launch_bounds__(256) void lif_kernel_v8(
    const float* __restrict__ x,
    const float* __restrict__ lat,
    const float* __restrict__ w,
    float4* __restrict__ out)
{
    long long g = (long long)blockIdx.x * blockDim.x + threadIdx.x;
    const float* xp = x   + g * 8;   // 32B-aligned: g*32 bytes from base
    const float* lp = lat + g * 8;

    const float thre = tanhf(w[0]);

    float4 x0, x1, l0, l1;
    ldg256(xp, x0, x1);
    ldg256(lp, l0, l1);

    float4 o0 = lif4(x0, l0, thre);
    float4 o1 = lif4(x1, l1, thre);

    __stcs(&out[g * 2],     o0);
    __stcs(&out[g * 2 + 1], o1);
}

// Fallback: one float4 (neuron) per thread, predicated.
__global__ __launch_bounds__(256) void lif_kernel_f4(
    const float4* __restrict__ x,
    const float4* __restrict__ lat,
    const float* __restrict__ w,
    float4* __restrict__ out,
    int n)
{
    int i = blockIdx.x * blockDim.x + threadIdx.x;
    if (i >= n) return;
    const float thre = tanhf(w[0]);
    float4 xv = __ldcs(&x[i]);
    float4 lv = __ldcs(&lat[i]);
    __stcs(&out[i], lif4(xv, lv, thre));
}

extern "C" void kernel_launch(void* const* d_in, const int* in_sizes, int n_in,
                              void* d_out, int out_size)
{
    const float* x   = (const float*)d_in[0];  // [B, N, T] float32, T=4
    const float* lat = (const float*)d_in[1];
    const float* w   = (const float*)d_in[2];  // scalar
    float4* out = (float4*)d_out;

    int n = in_sizes[0] / 4;     // neurons (B*N); each = one float4
    int block = 256;
    int per_block = block * 2;   // v8 path: 2 neurons per thread

    if (n % per_block == 0) {
        int grid = n / per_block;
        lif_kernel_v8<<<grid, block>>>(x, lat, w, out);
    } else {
        int grid = (n + block - 1) / block;
        lif_kernel_f4<<<grid, block>>>((const float4*)x, (const float4*)lat,
                                       w, out, n);
    }
}

// round 4
// speedup vs baseline: 1.0134x; 1.0134x over previous
#include <cuda_runtime.h>

// LIF neuron, T=4 unrolled, 2 neurons (float4s) per thread.
// Layout [B, N, T], T innermost -> one float4 per neuron.
// Fast path: exact division, zero predicates. Loads front-batched
// (2x LDG.E.128 per input array), streaming cache hints everywhere
// (strict read-once/write-once workload).
// Measured: ~108.6us kernel, DRAM ~88% SOL -> HBM streaming ceiling.

#define TAU 0.25f

__device__ __forceinline__ float4 lif4(float4 xv, float4 lv, float thre)
{
    float4 ov;
    float u = xv.x + lv.x;                 // t=0: u0=0 -> no decay term
    float o = (u > thre) ? u : 0.0f;
    ov.x = o;
    float reset = (o > thre) ? 0.0f : 1.0f;
    u = TAU * u * reset + xv.y + lv.y;     // t=1
    o = (u > thre) ? u : 0.0f;
    ov.y = o;
    reset = (o > thre) ? 0.0f : 1.0f;
    u = TAU * u * reset + xv.z + lv.z;     // t=2
    o = (u > thre) ? u : 0.0f;
    ov.z = o;
    reset = (o > thre) ? 0.0f : 1.0f;
    u = TAU * u * reset + xv.w + lv.w;     // t=3
    o = (u > thre) ? u : 0.0f;
    ov.w = o;
    return ov;
}

// Fast path: grid*blockDim*2 == n exactly; no predicates.
__global__ __launch_bounds__(256) void lif_kernel_exact(
    const float4* __restrict__ x,
    const float4* __restrict__ lat,
    const float* __restrict__ w,
    float4* __restrict__ out)
{
    int i0 = blockIdx.x * (blockDim.x * 2) + threadIdx.x;
    int i1 = i0 + blockDim.x;   // second contiguous 512B warp segment

    const float thre = tanhf(w[0]);

    // Front-batch all 4 loads (read-once: evict-first)
    float4 x0 = __ldcs(&x[i0]);
    float4 l0 = __ldcs(&lat[i0]);
    float4 x1 = __ldcs(&x[i1]);
    float4 l1 = __ldcs(&lat[i1]);

    __stcs(&out[i0], lif4(x0, l0, thre));
    __stcs(&out[i1], lif4(x1, l1, thre));
}

// Fallback: one float4 per thread, predicated (general sizes).
__global__ __launch_bounds__(256) void lif_kernel_f4(
    const float4* __restrict__ x,
    const float4* __restrict__ lat,
    const float* __restrict__ w,
    float4* __restrict__ out,
    int n)
{
    int i = blockIdx.x * blockDim.x + threadIdx.x;
    if (i >= n) return;
    const float thre = tanhf(w[0]);
    float4 xv = __ldcs(&x[i]);
    float4 lv = __ldcs(&lat[i]);
    __stcs(&out[i], lif4(xv, lv, thre));
}

extern "C" void kernel_launch(void* const* d_in, const int* in_sizes, int n_in,
                              void* d_out, int out_size)
{
    const float4* x   = (const float4*)d_in[0];  // [B, N, T] float32, T=4
    const float4* lat = (const float4*)d_in[1];
    const float*  w   = (const float*)d_in[2];   // scalar
    float4* out = (float4*)d_out;

    int n = in_sizes[0] / 4;     // neurons (B*N); one float4 each
    int block = 256;
    int per_block = block * 2;   // 2 neurons per thread

    if (n % per_block == 0) {
        lif_kernel_exact<<<n / per_block, block>>>(x, lat, w, out);
    } else {
        lif_kernel_f4<<<(n + block - 1) / block, block>>>(x, lat, w, out, n);
    }
}